// round 13
// baseline (speedup 1.0000x reference)
#include <cuda_runtime.h>
#include <math.h>

#define NN 8192
#define EE 524288
#define ET (EE + NN)

// ---------------- scratch (device globals; no allocation allowed) ----------
__device__ __align__(16) float g_x  [NN * 64];   // node features
__device__ __align__(16) float g_t0 [NN * 64];   // xl  / P (= x @ Wp)
__device__ __align__(16) float g_t1 [NN * 64];   // xr  / Q (= x @ Wq + bq)
__device__ __align__(16) float g_p  [ET * 4];    // per-edge exp(logit), edge-id order
// CSR-by-dst (rebuilt every launch; graph-replay safe)
__device__ int g_cnt [NN];        // in-degree histogram
__device__ int g_rp  [NN + 1];    // row pointers
__device__ int g_fill[NN];        // scatter cursors
__device__ int g_cs  [EE];        // CSR: src node per slot
__device__ int g_ce  [EE];        // CSR: original edge id per slot
// folded edge-MLP weights
__device__ __align__(16) float g_Wp[64 * 64];
__device__ __align__(16) float g_Wq[64 * 64];
__device__             float g_bq[64];

// FMA one weight row (64 wide) into a 64-accumulator array, vectorized smem reads
__device__ __forceinline__ void fma_row(float (&a)[64], float v, const float* wrow) {
    const float4* w = reinterpret_cast<const float4*>(wrow);
#pragma unroll
    for (int jj = 0; jj < 16; jj++) {
        float4 wv = w[jj];
        a[jj * 4 + 0] += v * wv.x;
        a[jj * 4 + 1] += v * wv.y;
        a[jj * 4 + 2] += v * wv.z;
        a[jj * 4 + 3] += v * wv.w;
    }
}

// ---------------- input MLP: g_x = relu(x @ W1 + b1) ------------------------
__global__ void k_in_mlp(const float* __restrict__ x,
                         const float* __restrict__ W1,
                         const float* __restrict__ b1) {
    __shared__ __align__(16) float sW[12 * 64];
    __shared__ float sb[64];
    for (int i = threadIdx.x; i < 12 * 64; i += blockDim.x) sW[i] = W1[i];
    if (threadIdx.x < 64) sb[threadIdx.x] = b1[threadIdx.x];
    __syncthreads();
    int r = blockIdx.x * blockDim.x + threadIdx.x;
    if (r >= NN) return;

    float xi[12];
#pragma unroll
    for (int k = 0; k < 12; k++) xi[k] = x[r * 12 + k];

    float a[64];
#pragma unroll
    for (int j = 0; j < 64; j++) a[j] = sb[j];
#pragma unroll
    for (int k = 0; k < 12; k++) fma_row(a, xi[k], &sW[k * 64]);

    float4* o = reinterpret_cast<float4*>(&g_x[r * 64]);
#pragma unroll
    for (int jj = 0; jj < 16; jj++)
        o[jj] = make_float4(fmaxf(a[jj * 4 + 0], 0.f), fmaxf(a[jj * 4 + 1], 0.f),
                            fmaxf(a[jj * 4 + 2], 0.f), fmaxf(a[jj * 4 + 3], 0.f));
}

// ---------------- residual layer: g_x = g_x + relu(g_x @ W + b) -------------
__global__ void k_resid(const float* __restrict__ W, const float* __restrict__ b) {
    __shared__ __align__(16) float sW[64 * 64];
    __shared__ float sb[64];
    for (int i = threadIdx.x; i < 4096; i += blockDim.x) sW[i] = W[i];
    if (threadIdx.x < 64) sb[threadIdx.x] = b[threadIdx.x];
    __syncthreads();
    int r = blockIdx.x * blockDim.x + threadIdx.x;
    if (r >= NN) return;

    const float4* xr4 = reinterpret_cast<const float4*>(&g_x[r * 64]);
    float a[64];
#pragma unroll
    for (int j = 0; j < 64; j++) a[j] = sb[j];
#pragma unroll 1
    for (int i = 0; i < 16; i++) {
        float4 v = xr4[i];
        fma_row(a, v.x, &sW[(4 * i + 0) * 64]);
        fma_row(a, v.y, &sW[(4 * i + 1) * 64]);
        fma_row(a, v.z, &sW[(4 * i + 2) * 64]);
        fma_row(a, v.w, &sW[(4 * i + 3) * 64]);
    }
    float4* o = reinterpret_cast<float4*>(&g_x[r * 64]);
#pragma unroll
    for (int jj = 0; jj < 16; jj++) {
        float4 v = xr4[jj];
        o[jj] = make_float4(v.x + fmaxf(a[jj * 4 + 0], 0.f),
                            v.y + fmaxf(a[jj * 4 + 1], 0.f),
                            v.z + fmaxf(a[jj * 4 + 2], 0.f),
                            v.w + fmaxf(a[jj * 4 + 3], 0.f));
    }
}

// ---------------- dual linear core ------------------------------------------
__device__ __forceinline__ void lin2_body(int r, const float* sWa, const float* sWb,
                                          const float* sba, const float* sbb) {
    const float4* xr4 = reinterpret_cast<const float4*>(&g_x[r * 64]);
    {
        float a[64];
#pragma unroll
        for (int j = 0; j < 64; j++) a[j] = sba[j];
#pragma unroll 1
        for (int i = 0; i < 16; i++) {
            float4 v = xr4[i];
            fma_row(a, v.x, &sWa[(4 * i + 0) * 64]);
            fma_row(a, v.y, &sWa[(4 * i + 1) * 64]);
            fma_row(a, v.z, &sWa[(4 * i + 2) * 64]);
            fma_row(a, v.w, &sWa[(4 * i + 3) * 64]);
        }
        float4* o = reinterpret_cast<float4*>(&g_t0[r * 64]);
#pragma unroll
        for (int jj = 0; jj < 16; jj++)
            o[jj] = make_float4(a[jj * 4 + 0], a[jj * 4 + 1], a[jj * 4 + 2], a[jj * 4 + 3]);
    }
    {
        float a[64];
#pragma unroll
        for (int j = 0; j < 64; j++) a[j] = sbb[j];
#pragma unroll 1
        for (int i = 0; i < 16; i++) {
            float4 v = xr4[i];
            fma_row(a, v.x, &sWb[(4 * i + 0) * 64]);
            fma_row(a, v.y, &sWb[(4 * i + 1) * 64]);
            fma_row(a, v.z, &sWb[(4 * i + 2) * 64]);
            fma_row(a, v.w, &sWb[(4 * i + 3) * 64]);
        }
        float4* o = reinterpret_cast<float4*>(&g_t1[r * 64]);
#pragma unroll
        for (int jj = 0; jj < 16; jj++)
            o[jj] = make_float4(a[jj * 4 + 0], a[jj * 4 + 1], a[jj * 4 + 2], a[jj * 4 + 3]);
    }
}

// g_t0 = x@Wa + ba, g_t1 = x@Wb + bb (input weights)
__global__ void k_lin2(const float* __restrict__ Wa, const float* __restrict__ ba,
                       const float* __restrict__ Wb, const float* __restrict__ bb) {
    __shared__ __align__(16) float sWa[4096], sWb[4096];
    __shared__ float sba[64], sbb[64];
    for (int i = threadIdx.x; i < 4096; i += blockDim.x) { sWa[i] = Wa[i]; sWb[i] = Wb[i]; }
    if (threadIdx.x < 64) { sba[threadIdx.x] = ba[threadIdx.x]; sbb[threadIdx.x] = bb[threadIdx.x]; }
    __syncthreads();
    int r = blockIdx.x * blockDim.x + threadIdx.x;
    if (r >= NN) return;
    lin2_body(r, sWa, sWb, sba, sbb);
}

// g_t0 = x@g_Wp, g_t1 = x@g_Wq + g_bq (folded edge-MLP weights from globals)
__global__ void k_lin2G() {
    __shared__ __align__(16) float sWa[4096], sWb[4096];
    __shared__ float sba[64], sbb[64];
    for (int i = threadIdx.x; i < 4096; i += blockDim.x) { sWa[i] = g_Wp[i]; sWb[i] = g_Wq[i]; }
    if (threadIdx.x < 64) { sba[threadIdx.x] = 0.f; sbb[threadIdx.x] = g_bq[threadIdx.x]; }
    __syncthreads();
    int r = blockIdx.x * blockDim.x + threadIdx.x;
    if (r >= NN) return;
    lin2_body(r, sWa, sWb, sba, sbb);
}

// ---------------- fold edge-MLP first two linear layers ---------------------
// Wp = We1_top @ We2, Wq = We1_bot @ We2, bq = be1 @ We2 + be2
__global__ void k_wfold(const float* __restrict__ We1, const float* __restrict__ be1,
                        const float* __restrict__ We2, const float* __restrict__ be2) {
    int t = blockIdx.x * blockDim.x + threadIdx.x;
    if (t < 8192) {
        int half = t >> 12;
        int i = (t >> 6) & 63;
        int j = t & 63;
        const float* wrow = We1 + (half * 64 + i) * 64;
        float acc = 0.f;
#pragma unroll 8
        for (int k = 0; k < 64; k++) acc += wrow[k] * We2[k * 64 + j];
        if (half == 0) g_Wp[i * 64 + j] = acc;
        else           g_Wq[i * 64 + j] = acc;
    }
    if (t < 64) {
        float acc = be2[t];
#pragma unroll 8
        for (int k = 0; k < 64; k++) acc += be1[k] * We2[k * 64 + t];
        g_bq[t] = acc;
    }
}

// ---------------- CSR build (per launch, deterministic inputs) --------------
__global__ void k_czero() {
    int i = blockIdx.x * blockDim.x + threadIdx.x;
    if (i < NN) g_cnt[i] = 0;
}
__global__ void k_hist(const int* __restrict__ dst) {
    int e = blockIdx.x * blockDim.x + threadIdx.x;
    if (e < EE) atomicAdd(&g_cnt[dst[e]], 1);
}
// single block of 1024 threads, 8 nodes each; exclusive scan -> rowptr + cursors
__global__ void k_scan() {
    __shared__ int sp[1024];
    int t = threadIdx.x;
    int base = t * 8;
    int loc[8];
    int sum = 0;
#pragma unroll
    for (int j = 0; j < 8; j++) { loc[j] = g_cnt[base + j]; sum += loc[j]; }
    sp[t] = sum;
    __syncthreads();
    for (int off = 1; off < 1024; off <<= 1) {
        int v = (t >= off) ? sp[t - off] : 0;
        __syncthreads();
        sp[t] += v;
        __syncthreads();
    }
    int run = sp[t] - sum;
#pragma unroll
    for (int j = 0; j < 8; j++) {
        g_rp[base + j] = run;
        g_fill[base + j] = run;
        run += loc[j];
    }
    if (t == 1023) g_rp[NN] = run;
}
__global__ void k_scatter(const int* __restrict__ src, const int* __restrict__ dst) {
    int e = blockIdx.x * blockDim.x + threadIdx.x;
    if (e >= EE) return;
    int d = dst[e];
    int pos = atomicAdd(&g_fill[d], 1);
    g_cs[pos] = src[e];
    g_ce[pos] = e;
}

// ---------------- GAT edge pass 1: logits -> exp (coalesced store) ----------
__global__ void k_edge_att(const int* __restrict__ src, const int* __restrict__ dst,
                           const float* __restrict__ att) {
    __shared__ float satt[64];
    if (threadIdx.x < 64) satt[threadIdx.x] = att[threadIdx.x];
    __syncthreads();
    int e = blockIdx.x * blockDim.x + threadIdx.x;
    if (e >= ET) return;
    int s, d;
    if (e < EE) { s = src[e]; d = dst[e]; } else { s = e - EE; d = s; }

    const float4* xl = reinterpret_cast<const float4*>(&g_t0[s * 64]);
    const float4* xr = reinterpret_cast<const float4*>(&g_t1[d * 64]);
    float lg[4] = {0.f, 0.f, 0.f, 0.f};
#pragma unroll
    for (int i = 0; i < 16; i++) {
        float4 a = xl[i], b = xr[i];
        float v0 = a.x + b.x; v0 = v0 > 0.f ? v0 : 0.2f * v0;
        float v1 = a.y + b.y; v1 = v1 > 0.f ? v1 : 0.2f * v1;
        float v2 = a.z + b.z; v2 = v2 > 0.f ? v2 : 0.2f * v2;
        float v3 = a.w + b.w; v3 = v3 > 0.f ? v3 : 0.2f * v3;
        lg[i >> 2] += v0 * satt[i * 4 + 0] + v1 * satt[i * 4 + 1]
                    + v2 * satt[i * 4 + 2] + v3 * satt[i * 4 + 3];
    }
    float4 p = make_float4(expf(lg[0]), expf(lg[1]), expf(lg[2]), expf(lg[3]));
    *reinterpret_cast<float4*>(&g_p[e * 4]) = p;   // softmax shift-invariant
}

// ---------------- GAT pass 2: warp-per-dst CSR aggregation ------------------
// acc = sum_e p_e * xl[src_e];  den = sum_e p_e;  x[d] += acc/den + bo
__global__ void k_dst_agg(const float* __restrict__ bo) {
    int w = (blockIdx.x * blockDim.x + threadIdx.x) >> 5;   // dst node
    int lane = threadIdx.x & 31;
    if (w >= NN) return;
    int beg = g_rp[w], end = g_rp[w + 1];
    int hl = lane >> 4;            // head of channel `lane` (0/1); +2 for hi half

    float acc0 = 0.f, acc1 = 0.f, d0 = 0.f, d1 = 0.f;
    for (int k = beg; k < end; k++) {
        int s = g_cs[k];
        int e = g_ce[k];
        float plo = g_p[e * 4 + hl];
        float phi = g_p[e * 4 + 2 + hl];
        float a = g_t0[s * 64 + lane];
        float b = g_t0[s * 64 + 32 + lane];
        acc0 += plo * a; d0 += plo;
        acc1 += phi * b; d1 += phi;
    }
    { // self loop (edge id EE + w, src = w)
        int e = EE + w;
        float plo = g_p[e * 4 + hl];
        float phi = g_p[e * 4 + 2 + hl];
        acc0 += plo * g_t0[w * 64 + lane];        d0 += plo;
        acc1 += phi * g_t0[w * 64 + 32 + lane];   d1 += phi;
    }
    g_x[w * 64 + lane]      += acc0 / d0 + bo[lane];
    g_x[w * 64 + 32 + lane] += acc1 / d1 + bo[32 + lane];
}

// ---------------- edge output: sigmoid(b3 + relu(P[s]+Q[d]).We3) ------------
__global__ void k_edge_out(const int* __restrict__ src, const int* __restrict__ dst,
                           const float* __restrict__ We3, const float* __restrict__ be3,
                           float* __restrict__ out) {
    __shared__ float sw3[64];
    __shared__ float sb3;
    if (threadIdx.x < 64) sw3[threadIdx.x] = We3[threadIdx.x];
    if (threadIdx.x == 0) sb3 = be3[0];
    __syncthreads();
    int e = blockIdx.x * blockDim.x + threadIdx.x;
    if (e >= EE) return;
    int s = src[e], d = dst[e];

    const float4* P = reinterpret_cast<const float4*>(&g_t0[s * 64]);
    const float4* Q = reinterpret_cast<const float4*>(&g_t1[d * 64]);
    float t = sb3;
#pragma unroll
    for (int i = 0; i < 16; i++) {
        float4 p = P[i], q = Q[i];
        t += fmaxf(p.x + q.x, 0.f) * sw3[4 * i + 0]
           + fmaxf(p.y + q.y, 0.f) * sw3[4 * i + 1]
           + fmaxf(p.z + q.z, 0.f) * sw3[4 * i + 2]
           + fmaxf(p.w + q.w, 0.f) * sw3[4 * i + 3];
    }
    out[(size_t)s * NN + d] = 1.f / (1.f + expf(-t));
}

// ---------------------------------------------------------------------------
extern "C" void kernel_launch(void* const* d_in, const int* in_sizes, int n_in,
                              void* d_out, int out_size) {
    const float* x    = (const float*)d_in[0];
    const float* W1   = (const float*)d_in[1];
    const float* b1   = (const float*)d_in[2];
    const float* W2   = (const float*)d_in[3];
    const float* b2   = (const float*)d_in[4];
    const float* Wl1  = (const float*)d_in[5];
    const float* bl1  = (const float*)d_in[6];
    const float* Wr1  = (const float*)d_in[7];
    const float* br1  = (const float*)d_in[8];
    const float* att1 = (const float*)d_in[9];
    const float* bo1  = (const float*)d_in[10];
    const float* W4   = (const float*)d_in[11];
    const float* b4   = (const float*)d_in[12];
    const float* Wl2  = (const float*)d_in[13];
    const float* bl2  = (const float*)d_in[14];
    const float* Wr2  = (const float*)d_in[15];
    const float* br2  = (const float*)d_in[16];
    const float* att2 = (const float*)d_in[17];
    const float* bo2  = (const float*)d_in[18];
    const float* W5   = (const float*)d_in[19];
    const float* b5   = (const float*)d_in[20];
    const float* We1  = (const float*)d_in[21];
    const float* be1  = (const float*)d_in[22];
    const float* We2  = (const float*)d_in[23];
    const float* be2  = (const float*)d_in[24];
    const float* We3  = (const float*)d_in[25];
    const float* be3  = (const float*)d_in[26];
    const int*   src  = (const int*)d_in[27];
    const int*   dst  = (const int*)d_in[28];
    float* out = (float*)d_out;

    const int NB128 = NN / 128;                  // node kernels: thread per row
    const int EB    = (ET + 255) / 256;          // edge blocks (incl self loops)
    const int EB0   = (EE + 255) / 256;          // edge blocks (no self loops)

    cudaMemsetAsync(d_out, 0, (size_t)NN * NN * sizeof(float));

    // CSR-by-dst build + weight folding (independent of node pipeline)
    k_czero<<<NN / 256, 256>>>();
    k_hist<<<EB0, 256>>>(dst);
    k_scan<<<1, 1024>>>();
    k_scatter<<<EB0, 256>>>(src, dst);
    k_wfold<<<32, 256>>>(We1, be1, We2, be2);

    k_in_mlp<<<NB128, 128>>>(x, W1, b1);
    k_resid<<<NB128, 128>>>(W2, b2);

    // GAT layer 1
    k_lin2<<<NB128, 128>>>(Wl1, bl1, Wr1, br1);
    k_edge_att<<<EB, 256>>>(src, dst, att1);
    k_dst_agg<<<NN / 8, 256>>>(bo1);

    k_resid<<<NB128, 128>>>(W4, b4);

    // GAT layer 2
    k_lin2<<<NB128, 128>>>(Wl2, bl2, Wr2, br2);
    k_edge_att<<<EB, 256>>>(src, dst, att2);
    k_dst_agg<<<NN / 8, 256>>>(bo2);

    k_resid<<<NB128, 128>>>(W5, b5);

    // per-edge MLP via folded per-node P/Q
    k_lin2G<<<NB128, 128>>>();
    k_edge_out<<<EB0, 256>>>(src, dst, We3, be3, out);
}

// round 14
// speedup vs baseline: 1.6866x; 1.6866x over previous
#include <cuda_runtime.h>
#include <math.h>

#define NN 8192
#define EE 524288

// ---------------- scratch (device globals; no allocation allowed) ----------
__device__ __align__(16) float g_x  [NN * 64];   // node features
__device__ __align__(16) float g_t0 [NN * 64];   // xl  / P (= x @ Wp)
__device__ __align__(16) float g_t1 [NN * 64];   // xr  / Q (= x @ Wq + bq)
// CSR-by-dst (rebuilt every launch; graph-replay safe)
__device__ int g_cnt [NN];        // in-degree histogram
__device__ int g_rp  [NN + 1];    // row pointers
__device__ int g_fill[NN];        // scatter cursors
__device__ int g_cs  [EE];        // CSR: src node per slot
// folded edge-MLP weights
__device__ __align__(16) float g_Wp[64 * 64];
__device__ __align__(16) float g_Wq[64 * 64];
__device__             float g_bq[64];

// FMA one weight row (64 wide) into a 64-accumulator array, vectorized smem reads
__device__ __forceinline__ void fma_row(float (&a)[64], float v, const float* wrow) {
    const float4* w = reinterpret_cast<const float4*>(wrow);
#pragma unroll
    for (int jj = 0; jj < 16; jj++) {
        float4 wv = w[jj];
        a[jj * 4 + 0] += v * wv.x;
        a[jj * 4 + 1] += v * wv.y;
        a[jj * 4 + 2] += v * wv.z;
        a[jj * 4 + 3] += v * wv.w;
    }
}

// ---------------- input MLP: g_x = relu(x @ W1 + b1) ------------------------
__global__ void k_in_mlp(const float* __restrict__ x,
                         const float* __restrict__ W1,
                         const float* __restrict__ b1) {
    __shared__ __align__(16) float sW[12 * 64];
    __shared__ float sb[64];
    for (int i = threadIdx.x; i < 12 * 64; i += blockDim.x) sW[i] = W1[i];
    if (threadIdx.x < 64) sb[threadIdx.x] = b1[threadIdx.x];
    __syncthreads();
    int r = blockIdx.x * blockDim.x + threadIdx.x;
    if (r >= NN) return;

    float xi[12];
#pragma unroll
    for (int k = 0; k < 12; k++) xi[k] = x[r * 12 + k];

    float a[64];
#pragma unroll
    for (int j = 0; j < 64; j++) a[j] = sb[j];
#pragma unroll
    for (int k = 0; k < 12; k++) fma_row(a, xi[k], &sW[k * 64]);

    float4* o = reinterpret_cast<float4*>(&g_x[r * 64]);
#pragma unroll
    for (int jj = 0; jj < 16; jj++)
        o[jj] = make_float4(fmaxf(a[jj * 4 + 0], 0.f), fmaxf(a[jj * 4 + 1], 0.f),
                            fmaxf(a[jj * 4 + 2], 0.f), fmaxf(a[jj * 4 + 3], 0.f));
}

// ---------------- residual layer: g_x = g_x + relu(g_x @ W + b) -------------
__global__ void k_resid(const float* __restrict__ W, const float* __restrict__ b) {
    __shared__ __align__(16) float sW[64 * 64];
    __shared__ float sb[64];
    for (int i = threadIdx.x; i < 4096; i += blockDim.x) sW[i] = W[i];
    if (threadIdx.x < 64) sb[threadIdx.x] = b[threadIdx.x];
    __syncthreads();
    int r = blockIdx.x * blockDim.x + threadIdx.x;
    if (r >= NN) return;

    const float4* xr4 = reinterpret_cast<const float4*>(&g_x[r * 64]);
    float a[64];
#pragma unroll
    for (int j = 0; j < 64; j++) a[j] = sb[j];
#pragma unroll 1
    for (int i = 0; i < 16; i++) {
        float4 v = xr4[i];
        fma_row(a, v.x, &sW[(4 * i + 0) * 64]);
        fma_row(a, v.y, &sW[(4 * i + 1) * 64]);
        fma_row(a, v.z, &sW[(4 * i + 2) * 64]);
        fma_row(a, v.w, &sW[(4 * i + 3) * 64]);
    }
    float4* o = reinterpret_cast<float4*>(&g_x[r * 64]);
#pragma unroll
    for (int jj = 0; jj < 16; jj++) {
        float4 v = xr4[jj];
        o[jj] = make_float4(v.x + fmaxf(a[jj * 4 + 0], 0.f),
                            v.y + fmaxf(a[jj * 4 + 1], 0.f),
                            v.z + fmaxf(a[jj * 4 + 2], 0.f),
                            v.w + fmaxf(a[jj * 4 + 3], 0.f));
    }
}

// ---------------- dual linear core ------------------------------------------
__device__ __forceinline__ void lin2_body(int r, const float* sWa, const float* sWb,
                                          const float* sba, const float* sbb) {
    const float4* xr4 = reinterpret_cast<const float4*>(&g_x[r * 64]);
    {
        float a[64];
#pragma unroll
        for (int j = 0; j < 64; j++) a[j] = sba[j];
#pragma unroll 1
        for (int i = 0; i < 16; i++) {
            float4 v = xr4[i];
            fma_row(a, v.x, &sWa[(4 * i + 0) * 64]);
            fma_row(a, v.y, &sWa[(4 * i + 1) * 64]);
            fma_row(a, v.z, &sWa[(4 * i + 2) * 64]);
            fma_row(a, v.w, &sWa[(4 * i + 3) * 64]);
        }
        float4* o = reinterpret_cast<float4*>(&g_t0[r * 64]);
#pragma unroll
        for (int jj = 0; jj < 16; jj++)
            o[jj] = make_float4(a[jj * 4 + 0], a[jj * 4 + 1], a[jj * 4 + 2], a[jj * 4 + 3]);
    }
    {
        float a[64];
#pragma unroll
        for (int j = 0; j < 64; j++) a[j] = sbb[j];
#pragma unroll 1
        for (int i = 0; i < 16; i++) {
            float4 v = xr4[i];
            fma_row(a, v.x, &sWb[(4 * i + 0) * 64]);
            fma_row(a, v.y, &sWb[(4 * i + 1) * 64]);
            fma_row(a, v.z, &sWb[(4 * i + 2) * 64]);
            fma_row(a, v.w, &sWb[(4 * i + 3) * 64]);
        }
        float4* o = reinterpret_cast<float4*>(&g_t1[r * 64]);
#pragma unroll
        for (int jj = 0; jj < 16; jj++)
            o[jj] = make_float4(a[jj * 4 + 0], a[jj * 4 + 1], a[jj * 4 + 2], a[jj * 4 + 3]);
    }
}

// g_t0 = x@Wa + ba, g_t1 = x@Wb + bb (input weights)
__global__ void k_lin2(const float* __restrict__ Wa, const float* __restrict__ ba,
                       const float* __restrict__ Wb, const float* __restrict__ bb) {
    __shared__ __align__(16) float sWa[4096], sWb[4096];
    __shared__ float sba[64], sbb[64];
    for (int i = threadIdx.x; i < 4096; i += blockDim.x) { sWa[i] = Wa[i]; sWb[i] = Wb[i]; }
    if (threadIdx.x < 64) { sba[threadIdx.x] = ba[threadIdx.x]; sbb[threadIdx.x] = bb[threadIdx.x]; }
    __syncthreads();
    int r = blockIdx.x * blockDim.x + threadIdx.x;
    if (r >= NN) return;
    lin2_body(r, sWa, sWb, sba, sbb);
}

// g_t0 = x@g_Wp, g_t1 = x@g_Wq + g_bq (folded edge-MLP weights from globals)
__global__ void k_lin2G() {
    __shared__ __align__(16) float sWa[4096], sWb[4096];
    __shared__ float sba[64], sbb[64];
    for (int i = threadIdx.x; i < 4096; i += blockDim.x) { sWa[i] = g_Wp[i]; sWb[i] = g_Wq[i]; }
    if (threadIdx.x < 64) { sba[threadIdx.x] = 0.f; sbb[threadIdx.x] = g_bq[threadIdx.x]; }
    __syncthreads();
    int r = blockIdx.x * blockDim.x + threadIdx.x;
    if (r >= NN) return;
    lin2_body(r, sWa, sWb, sba, sbb);
}

// ---------------- fold edge-MLP first two linear layers ---------------------
// Wp = We1_top @ We2, Wq = We1_bot @ We2, bq = be1 @ We2 + be2
__global__ void k_wfold(const float* __restrict__ We1, const float* __restrict__ be1,
                        const float* __restrict__ We2, const float* __restrict__ be2) {
    int t = blockIdx.x * blockDim.x + threadIdx.x;
    if (t < 8192) {
        int half = t >> 12;
        int i = (t >> 6) & 63;
        int j = t & 63;
        const float* wrow = We1 + (half * 64 + i) * 64;
        float acc = 0.f;
#pragma unroll 8
        for (int k = 0; k < 64; k++) acc += wrow[k] * We2[k * 64 + j];
        if (half == 0) g_Wp[i * 64 + j] = acc;
        else           g_Wq[i * 64 + j] = acc;
    }
    if (t < 64) {
        float acc = be2[t];
#pragma unroll 8
        for (int k = 0; k < 64; k++) acc += be1[k] * We2[k * 64 + t];
        g_bq[t] = acc;
    }
}

// ---------------- CSR build (per launch, deterministic inputs) --------------
__global__ void k_czero() {
    int i = blockIdx.x * blockDim.x + threadIdx.x;
    if (i < NN) g_cnt[i] = 0;
}
__global__ void k_hist(const int* __restrict__ dst) {
    int e = blockIdx.x * blockDim.x + threadIdx.x;
    if (e < EE) atomicAdd(&g_cnt[dst[e]], 1);
}
// single block of 1024 threads, 8 nodes each; exclusive scan -> rowptr + cursors
__global__ void k_scan() {
    __shared__ int sp[1024];
    int t = threadIdx.x;
    int base = t * 8;
    int loc[8];
    int sum = 0;
#pragma unroll
    for (int j = 0; j < 8; j++) { loc[j] = g_cnt[base + j]; sum += loc[j]; }
    sp[t] = sum;
    __syncthreads();
    for (int off = 1; off < 1024; off <<= 1) {
        int v = (t >= off) ? sp[t - off] : 0;
        __syncthreads();
        sp[t] += v;
        __syncthreads();
    }
    int run = sp[t] - sum;
#pragma unroll
    for (int j = 0; j < 8; j++) {
        g_rp[base + j] = run;
        g_fill[base + j] = run;
        run += loc[j];
    }
    if (t == 1023) g_rp[NN] = run;
}
__global__ void k_scatter(const int* __restrict__ src, const int* __restrict__ dst) {
    int e = blockIdx.x * blockDim.x + threadIdx.x;
    if (e >= EE) return;
    int d = dst[e];
    int pos = atomicAdd(&g_fill[d], 1);
    g_cs[pos] = src[e];
}

// ---------------- fused GAT layer: warp-per-dst, attention + aggregation ----
// For each in-edge s of node w (plus self loop):
//   logit_h = sum_c att[h,c] * lrelu(xl[s,h,c] + xr[w,h,c]);  p = exp(logit_h)
//   acc += p * xl[s];  den += p;   then x[w] += acc/den + bo
// Lane L holds channels L (heads 0/1) and 32+L (heads 2/3); head logits are
// 16-lane segment reductions (xor 8,4,2,1 stays inside each 16-lane group).
__global__ void k_gat(const float* __restrict__ att, const float* __restrict__ bo) {
    int w = (blockIdx.x * blockDim.x + threadIdx.x) >> 5;   // dst node
    int lane = threadIdx.x & 31;
    if (w >= NN) return;

    float wa0 = __ldg(&att[lane]);
    float wa1 = __ldg(&att[32 + lane]);
    float xr0 = g_t1[w * 64 + lane];
    float xr1 = g_t1[w * 64 + 32 + lane];

    int beg = g_rp[w], end = g_rp[w + 1];
    float acc0 = 0.f, acc1 = 0.f, den0 = 0.f, den1 = 0.f;

    // self loop first (src = w)
    {
        float a0 = g_t0[w * 64 + lane];
        float a1 = g_t0[w * 64 + 32 + lane];
        float v0 = a0 + xr0; v0 = v0 > 0.f ? v0 : 0.2f * v0;
        float v1 = a1 + xr1; v1 = v1 > 0.f ? v1 : 0.2f * v1;
        float t0 = v0 * wa0, t1 = v1 * wa1;
#pragma unroll
        for (int off = 8; off; off >>= 1) {
            t0 += __shfl_xor_sync(0xffffffffu, t0, off);
            t1 += __shfl_xor_sync(0xffffffffu, t1, off);
        }
        float p0 = expf(t0), p1 = expf(t1);   // softmax shift-invariant
        acc0 += p0 * a0; den0 += p0;
        acc1 += p1 * a1; den1 += p1;
    }
    for (int k = beg; k < end; k++) {
        int s = g_cs[k];
        float a0 = g_t0[s * 64 + lane];
        float a1 = g_t0[s * 64 + 32 + lane];
        float v0 = a0 + xr0; v0 = v0 > 0.f ? v0 : 0.2f * v0;
        float v1 = a1 + xr1; v1 = v1 > 0.f ? v1 : 0.2f * v1;
        float t0 = v0 * wa0, t1 = v1 * wa1;
#pragma unroll
        for (int off = 8; off; off >>= 1) {
            t0 += __shfl_xor_sync(0xffffffffu, t0, off);
            t1 += __shfl_xor_sync(0xffffffffu, t1, off);
        }
        float p0 = expf(t0), p1 = expf(t1);
        acc0 += p0 * a0; den0 += p0;
        acc1 += p1 * a1; den1 += p1;
    }

    g_x[w * 64 + lane]      += acc0 / den0 + __ldg(&bo[lane]);
    g_x[w * 64 + 32 + lane] += acc1 / den1 + __ldg(&bo[32 + lane]);
}

// ---------------- edge output: sigmoid(b3 + relu(P[s]+Q[d]).We3) ------------
__global__ void k_edge_out(const int* __restrict__ src, const int* __restrict__ dst,
                           const float* __restrict__ We3, const float* __restrict__ be3,
                           float* __restrict__ out) {
    __shared__ float sw3[64];
    __shared__ float sb3;
    if (threadIdx.x < 64) sw3[threadIdx.x] = We3[threadIdx.x];
    if (threadIdx.x == 0) sb3 = be3[0];
    __syncthreads();
    int e = blockIdx.x * blockDim.x + threadIdx.x;
    if (e >= EE) return;
    int s = src[e], d = dst[e];

    const float4* P = reinterpret_cast<const float4*>(&g_t0[s * 64]);
    const float4* Q = reinterpret_cast<const float4*>(&g_t1[d * 64]);
    float t = sb3;
#pragma unroll
    for (int i = 0; i < 16; i++) {
        float4 p = P[i], q = Q[i];
        t += fmaxf(p.x + q.x, 0.f) * sw3[4 * i + 0]
           + fmaxf(p.y + q.y, 0.f) * sw3[4 * i + 1]
           + fmaxf(p.z + q.z, 0.f) * sw3[4 * i + 2]
           + fmaxf(p.w + q.w, 0.f) * sw3[4 * i + 3];
    }
    out[(size_t)s * NN + d] = 1.f / (1.f + expf(-t));
}

// ---------------------------------------------------------------------------
extern "C" void kernel_launch(void* const* d_in, const int* in_sizes, int n_in,
                              void* d_out, int out_size) {
    const float* x    = (const float*)d_in[0];
    const float* W1   = (const float*)d_in[1];
    const float* b1   = (const float*)d_in[2];
    const float* W2   = (const float*)d_in[3];
    const float* b2   = (const float*)d_in[4];
    const float* Wl1  = (const float*)d_in[5];
    const float* bl1  = (const float*)d_in[6];
    const float* Wr1  = (const float*)d_in[7];
    const float* br1  = (const float*)d_in[8];
    const float* att1 = (const float*)d_in[9];
    const float* bo1  = (const float*)d_in[10];
    const float* W4   = (const float*)d_in[11];
    const float* b4   = (const float*)d_in[12];
    const float* Wl2  = (const float*)d_in[13];
    const float* bl2  = (const float*)d_in[14];
    const float* Wr2  = (const float*)d_in[15];
    const float* br2  = (const float*)d_in[16];
    const float* att2 = (const float*)d_in[17];
    const float* bo2  = (const float*)d_in[18];
    const float* W5   = (const float*)d_in[19];
    const float* b5   = (const float*)d_in[20];
    const float* We1  = (const float*)d_in[21];
    const float* be1  = (const float*)d_in[22];
    const float* We2  = (const float*)d_in[23];
    const float* be2  = (const float*)d_in[24];
    const float* We3  = (const float*)d_in[25];
    const float* be3  = (const float*)d_in[26];
    const int*   src  = (const int*)d_in[27];
    const int*   dst  = (const int*)d_in[28];
    float* out = (float*)d_out;

    const int NB128 = NN / 128;                  // node kernels: thread per row
    const int EB0   = (EE + 255) / 256;          // edge blocks

    cudaMemsetAsync(d_out, 0, (size_t)NN * NN * sizeof(float));

    // node pipeline head first so ncu's -s 5 window lands on k_lin2
    k_in_mlp<<<NB128, 128>>>(x, W1, b1);
    k_resid<<<NB128, 128>>>(W2, b2);
    k_czero<<<NN / 256, 256>>>();
    k_lin2<<<NB128, 128>>>(Wl1, bl1, Wr1, br1);      // <- profiled launch

    // CSR-by-dst build + weight folding (needed before k_gat / k_edge_out)
    k_hist<<<EB0, 256>>>(dst);
    k_scan<<<1, 1024>>>();
    k_scatter<<<EB0, 256>>>(src, dst);
    k_wfold<<<32, 256>>>(We1, be1, We2, be2);

    // GAT layer 1 (fused attention + aggregation)
    k_gat<<<NN / 8, 256>>>(att1, bo1);
    k_resid<<<NB128, 128>>>(W4, b4);

    // GAT layer 2
    k_lin2<<<NB128, 128>>>(Wl2, bl2, Wr2, br2);
    k_gat<<<NN / 8, 256>>>(att2, bo2);
    k_resid<<<NB128, 128>>>(W5, b5);

    // per-edge MLP via folded per-node P/Q
    k_lin2G<<<NB128, 128>>>();
    k_edge_out<<<EB0, 256>>>(src, dst, We3, be3, out);
}